// round 5
// baseline (speedup 1.0000x reference)
#include <cuda_runtime.h>

// Problem constants (fixed by reference setup)
#define BB 8
#define CC 32
#define NN 4096
#define TM 128      // m-columns per CTA
#define KN 64       // n-chunk per iteration
#define NTHREADS 128

// scratch for channel means: c_adj[b][n]
__device__ float g_cadj[BB * NN];

// Kernel 1: c_adj[b][n] = mean_c x[b][c][n]
__global__ void cadj_kernel(const float* __restrict__ x) {
    int idx = blockIdx.x * blockDim.x + threadIdx.x;  // over B*N
    if (idx >= BB * NN) return;
    int b = idx / NN;
    int n = idx - b * NN;
    const float* p = x + (size_t)b * CC * NN + n;
    float s = 0.f;
#pragma unroll
    for (int c = 0; c < CC; c++) s += p[(size_t)c * NN];
    g_cadj[idx] = s * (1.0f / CC);
}

// Kernel 2: fused A-construction + GEMM + para*relu epilogue.
// out[b,c,m] = relu( para[c,m] * sum_n fea[b,c,n] * adj[n,m] * 2/(1+exp(|cm-cn|)) )
__global__ __launch_bounds__(NTHREADS) void gcn_kernel(
    const float* __restrict__ x, const float* __restrict__ para,
    const float* __restrict__ adj, float* __restrict__ out)
{
    __shared__ float s_a[KN][TM];    // adj * s factor tile  (32 KB)
    __shared__ float s_fea[CC][KN];  // fea chunk            (8 KB)
    __shared__ float s_cm[TM];       // c_adj for this m-tile

    const int b  = blockIdx.y;
    const int m0 = blockIdx.x * TM;
    const int t  = threadIdx.x;
    const int tx = t & 31;   // m-group: owns m0 + tx + 32k, k=0..3
    const int ty = t >> 5;   // channel-group: owns c = ty*8 + j, j=0..7

    if (t < TM) s_cm[t] = g_cadj[b * NN + m0 + t];

    float acc[8][4];
#pragma unroll
    for (int j = 0; j < 8; j++)
#pragma unroll
        for (int k = 0; k < 4; k++) acc[j][k] = 0.f;

    __syncthreads();

    for (int n0 = 0; n0 < NN; n0 += KN) {
        // ---- stage fea chunk: s_fea[c][i] = x[b][c][n0+i] ----
#pragma unroll
        for (int r = 0; r < (CC * KN) / NTHREADS; r++) {
            int idx = t + r * NTHREADS;
            int c = idx / KN, i = idx - c * KN;
            s_fea[c][i] = x[((size_t)b * CC + c) * NN + n0 + i];
        }
        // ---- stage fused A tile: s_a[i][m] = adj[n0+i][m0+m] * 2/(1+e^|d|) ----
#pragma unroll
        for (int r = 0; r < (KN * TM) / NTHREADS; r++) {
            int idx = t + r * NTHREADS;     // i = r, m = t  (TM == NTHREADS)
            int i = idx / TM, m = idx - i * TM;
            float cn = g_cadj[b * NN + n0 + i];
            float d  = fabsf(s_cm[m] - cn);
            float sf = __fdividef(2.0f, 1.0f + __expf(d));
            s_a[i][m] = adj[(size_t)(n0 + i) * NN + m0 + m] * sf;
        }
        __syncthreads();

        // ---- inner product: 12 LDS + 32 FFMA per n per thread ----
#pragma unroll 4
        for (int i = 0; i < KN; i++) {
            float av[4], fv[8];
#pragma unroll
            for (int k = 0; k < 4; k++) av[k] = s_a[i][tx + 32 * k];
#pragma unroll
            for (int j = 0; j < 8; j++) fv[j] = s_fea[ty * 8 + j][i];
#pragma unroll
            for (int j = 0; j < 8; j++)
#pragma unroll
                for (int k = 0; k < 4; k++)
                    acc[j][k] = fmaf(fv[j], av[k], acc[j][k]);
        }
        __syncthreads();  // protect smem reuse next chunk
    }

    // ---- epilogue: * para, relu ----
#pragma unroll
    for (int j = 0; j < 8; j++) {
        int c = ty * 8 + j;
#pragma unroll
        for (int k = 0; k < 4; k++) {
            int m = m0 + tx + 32 * k;
            float v = acc[j][k] * para[(size_t)c * NN + m];
            out[((size_t)b * CC + c) * NN + m] = fmaxf(v, 0.f);
        }
    }
}

extern "C" void kernel_launch(void* const* d_in, const int* in_sizes, int n_in,
                              void* d_out, int out_size) {
    const float* x    = (const float*)d_in[0];  // [8,32,64,64]
    const float* para = (const float*)d_in[1];  // [1,32,64,64]
    const float* adj  = (const float*)d_in[2];  // [4096,4096]
    float* out = (float*)d_out;

    cadj_kernel<<<(BB * NN) / 256, 256>>>(x);
    dim3 grid(NN / TM, BB);  // 32 x 8 = 256 CTAs
    gcn_kernel<<<grid, NTHREADS>>>(x, para, adj, out);
}

// round 10
// speedup vs baseline: 1.4664x; 1.4664x over previous
#include <cuda_runtime.h>
#include <cstdint>

#define BB 8
#define CC 32
#define NN 4096
#define TM 128
#define KN 32
#define NCHUNK (NN / KN)   // 128

// packed per-node exp(mean), exp(-mean)
__device__ float2 g_EI[BB * NN];

// ---------------- Kernel 1: channel means -> (E, iE) -------------------------
__global__ void prep_kernel(const float* __restrict__ x) {
    int idx = blockIdx.x * blockDim.x + threadIdx.x;   // over B*N
    if (idx >= BB * NN) return;
    int b = idx / NN;
    int n = idx - b * NN;
    const float* p = x + (size_t)b * CC * NN + n;
    float s = 0.f;
#pragma unroll
    for (int c = 0; c < CC; c++) s += p[(size_t)c * NN];
    s *= (1.0f / CC);
    g_EI[idx] = make_float2(__expf(s), __expf(-s));
}

__device__ __forceinline__ uint32_t f2tf(float f) {
    uint32_t u;
    asm("cvt.rna.tf32.f32 %0, %1;" : "=r"(u) : "f"(f));
    return u;
}

// ---------------- Kernel 2: mma.sync tf32 fused GCN --------------------------
// D[m, c] = sum_n Ag[m,n] * fea[c,n],  Ag[m,n] = adj[m][n] * 2/(1+exp(|cm-cn|))
// (adj symmetric in this problem; sf symmetric exactly — validated in R5)
__global__ __launch_bounds__(256, 2) void gcn_mma_kernel(
    const float* __restrict__ x, const float* __restrict__ para,
    const float* __restrict__ adj, float* __restrict__ out)
{
    // B fragments for one 32-n chunk, fragment-ordered: [ks(4)][nt(4)][lane(32)]
    __shared__ float2 sB[512];   // 4 KB, values already tf32-rounded
    __shared__ float2 sE[KN];    // (En, iEn) for the chunk

    const int m0   = blockIdx.x * TM;
    const int b    = blockIdx.y;
    const int t    = threadIdx.x;
    const int w    = t >> 5;
    const int lane = t & 31;
    const int gr   = lane >> 2;   // fragment row group
    const int tc   = lane & 3;    // fragment col-in-group

    const float*  fea = x + (size_t)b * CC * NN;
    const float2* EIb = g_EI + b * NN;

    // ---- B staging slot mapping: 512 slots, 2 per thread ----
    const int s0i = t,        s1i = t + 256;
    const int c0s = (((s0i >> 5) & 3) << 3) + ((s0i & 31) >> 2);
    const int k0s = (((s0i >> 7) & 3) << 3) + (s0i & 3);
    const int c1s = (((s1i >> 5) & 3) << 3) + ((s1i & 31) >> 2);
    const int k1s = (((s1i >> 7) & 3) << 3) + (s1i & 3);
    const float* fp0 = fea + (size_t)c0s * NN + k0s;
    const float* fp1 = fea + (size_t)c1s * NN + k1s;

    // ---- per-warp m-row exp values (fixed for whole kernel) ----
    const float2 e0 = EIb[m0 + 16 * w + gr];
    const float2 e1 = EIb[m0 + 16 * w + gr + 8];
    const float Em0 = e0.x, iEm0 = e0.y, Em1 = e1.x, iEm1 = e1.y;

    // adj row base for this thread's fragment rows (row gr; row gr+8 at +8*NN)
    const float* adjp = adj + (size_t)(m0 + 16 * w + gr) * NN;

    float acc[4][4];
#pragma unroll
    for (int i = 0; i < 4; i++)
#pragma unroll
        for (int j = 0; j < 4; j++) acc[i][j] = 0.f;

    // ---- stage chunk 0 ----
    {
        float a0 = fp0[0], a1 = fp0[4], c0 = fp1[0], c1 = fp1[4];
        sB[s0i] = make_float2(__uint_as_float(f2tf(a0)), __uint_as_float(f2tf(a1)));
        sB[s1i] = make_float2(__uint_as_float(f2tf(c0)), __uint_as_float(f2tf(c1)));
        if (t < KN) sE[t] = EIb[t];
    }
    __syncthreads();

    for (int ch = 0; ch < NCHUNK; ch++) {
        const int n0 = ch * KN;
        const bool more = (ch + 1 < NCHUNK);

        // ---- prefetch next chunk's staging data into registers ----
        float pf00, pf01, pf10, pf11;
        float2 pfe;
        if (more) {
            const int n1 = n0 + KN;
            pf00 = fp0[n1]; pf01 = fp0[n1 + 4];
            pf10 = fp1[n1]; pf11 = fp1[n1 + 4];
            if (t < KN) pfe = EIb[n1 + t];
        }

        // ---- 4 k-steps of 8 over this chunk ----
#pragma unroll
        for (int ks = 0; ks < 4; ks++) {
            // E values at fragment cols tc, tc+4 (broadcast LDS)
            const float2 en0 = sE[ks * 8 + tc];
            const float2 en1 = sE[ks * 8 + tc + 4];
            // adj at the 4 fragment positions (sector-aligned pairs)
            const float* ap = adjp + n0 + ks * 8 + tc;
            const float ad00 = ap[0];
            const float ad10 = ap[(size_t)8 * NN];
            const float ad01 = ap[4];
            const float ad11 = ap[(size_t)8 * NN + 4];

            // construct Ag fragments: 2*adj / (1 + exp|cm-cn|)
            float tt;
            tt = fmaxf(Em0 * en0.y, en0.x * iEm0);
            const uint32_t A0 = f2tf(__fdividef(ad00 + ad00, 1.0f + tt));
            tt = fmaxf(Em1 * en0.y, en0.x * iEm1);
            const uint32_t A1 = f2tf(__fdividef(ad10 + ad10, 1.0f + tt));
            tt = fmaxf(Em0 * en1.y, en1.x * iEm0);
            const uint32_t A2 = f2tf(__fdividef(ad01 + ad01, 1.0f + tt));
            tt = fmaxf(Em1 * en1.y, en1.x * iEm1);
            const uint32_t A3 = f2tf(__fdividef(ad11 + ad11, 1.0f + tt));

#pragma unroll
            for (int nt = 0; nt < 4; nt++) {
                const float2 bb = sB[(ks * 4 + nt) * 32 + lane];
                const uint32_t B0 = __float_as_uint(bb.x);
                const uint32_t B1 = __float_as_uint(bb.y);
                asm volatile(
                    "mma.sync.aligned.m16n8k8.row.col.f32.tf32.tf32.f32 "
                    "{%0,%1,%2,%3}, {%4,%5,%6,%7}, {%8,%9}, {%0,%1,%2,%3};"
                    : "+f"(acc[nt][0]), "+f"(acc[nt][1]),
                      "+f"(acc[nt][2]), "+f"(acc[nt][3])
                    : "r"(A0), "r"(A1), "r"(A2), "r"(A3), "r"(B0), "r"(B1));
            }
        }

        __syncthreads();   // all warps done reading sB/sE
        if (more) {
            sB[s0i] = make_float2(__uint_as_float(f2tf(pf00)), __uint_as_float(f2tf(pf01)));
            sB[s1i] = make_float2(__uint_as_float(f2tf(pf10)), __uint_as_float(f2tf(pf11)));
            if (t < KN) sE[t] = pfe;
        }
        __syncthreads();   // staged data visible
    }

    // ---- epilogue: para * acc, relu, direct STG from accumulators ----
    const int mr0 = m0 + 16 * w + gr;
    const int mr1 = mr0 + 8;
#pragma unroll
    for (int nt = 0; nt < 4; nt++) {
        const int cA = nt * 8 + 2 * tc;
        const int cB = cA + 1;
        out[(size_t)(b * CC + cA) * NN + mr0] = fmaxf(acc[nt][0] * para[cA * NN + mr0], 0.f);
        out[(size_t)(b * CC + cB) * NN + mr0] = fmaxf(acc[nt][1] * para[cB * NN + mr0], 0.f);
        out[(size_t)(b * CC + cA) * NN + mr1] = fmaxf(acc[nt][2] * para[cA * NN + mr1], 0.f);
        out[(size_t)(b * CC + cB) * NN + mr1] = fmaxf(acc[nt][3] * para[cB * NN + mr1], 0.f);
    }
}

extern "C" void kernel_launch(void* const* d_in, const int* in_sizes, int n_in,
                              void* d_out, int out_size) {
    const float* x    = (const float*)d_in[0];  // [8,32,64,64]
    const float* para = (const float*)d_in[1];  // [1,32,64,64]
    const float* adj  = (const float*)d_in[2];  // [4096,4096]
    float* out = (float*)d_out;

    prep_kernel<<<(BB * NN) / 256, 256>>>(x);
    dim3 grid(NN / TM, BB);                     // 32 x 8 = 256 CTAs
    gcn_mma_kernel<<<grid, 256>>>(x, para, adj, out);
}

// round 11
// speedup vs baseline: 2.3489x; 1.6018x over previous
#include <cuda_runtime.h>
#include <cstdint>

#define BB 8
#define CC 32
#define NN 4096
#define TM 128
#define KN 32
#define NCHUNK (NN / KN)   // 128
#define NTH 128

// packed per-node exp(mean), exp(-mean)
__device__ float2 g_EI[BB * NN];

// ---------------- Kernel 1: channel means -> (E, iE) -------------------------
__global__ void prep_kernel(const float* __restrict__ x) {
    int idx = blockIdx.x * blockDim.x + threadIdx.x;   // over B*N
    if (idx >= BB * NN) return;
    int b = idx / NN;
    int n = idx - b * NN;
    const float* p = x + (size_t)b * CC * NN + n;
    float s = 0.f;
#pragma unroll
    for (int c = 0; c < CC; c++) s += p[(size_t)c * NN];
    s *= (1.0f / CC);
    g_EI[idx] = make_float2(__expf(s), __expf(-s));
}

__device__ __forceinline__ uint32_t f2tf(float f) {
    uint32_t u;
    asm("cvt.rna.tf32.f32 %0, %1;" : "=r"(u) : "f"(f));
    return u;
}
__device__ __forceinline__ float f2tff(float f) { return __uint_as_float(f2tf(f)); }

// ---------------- Kernel 2: SMEM-staged mma.sync tf32 fused GCN --------------
// D[m, c] = sum_n Ag[m,n] * fea[c,n],  Ag[m,n] = adj[m][n] * 2/(1+exp(|cm-cn|))
// (adj symmetric in this problem; sf exactly symmetric — validated R5/R10)
// 128 threads / 4 warps; warp w owns m-rows [32w, 32w+32) (two m16 tiles).
__global__ __launch_bounds__(NTH) void gcn_mma_kernel(
    const float* __restrict__ x, const float* __restrict__ para,
    const float* __restrict__ adj, float* __restrict__ out)
{
    // Ag tile [128 m][32 n], XOR-swizzled: word = m*32 + ((n&~3)^((m&7)<<2)) + (n&3)
    __shared__ float sA[TM * KN];        // 16 KB
    // fea fragments: [nt(4)][ks(4)][lane(32)] float2 = (fea[c][k], fea[c][k+4])
    __shared__ float2 sB[512];           // 4 KB

    const int b    = blockIdx.y;
    const int m0   = blockIdx.x * TM;
    const int t    = threadIdx.x;
    const int w    = t >> 5;
    const int lane = t & 31;
    const int gr   = lane >> 2;
    const int tc   = lane & 3;

    const float*  fea = x + (size_t)b * CC * NN;
    const float2* EIb = g_EI + b * NN;

    // --- construction role: thread owns rows m = r*16 + cr (r=0..7), col quad n4 ---
    const int cr = t >> 3;     // 0..15
    const int n4 = t & 7;      // 0..7
    // --- B staging role: thread owns channel sc, kstep sks ---
    const int sc  = t >> 2;    // 0..31
    const int sks = t & 3;     // 0..3

    // per-thread m-row exp pairs, invariant over chunks
    float2 Em[8];
#pragma unroll
    for (int r = 0; r < 8; r++) Em[r] = EIb[m0 + r * 16 + cr];

    const float* adjbase = adj + (size_t)(m0 + cr) * NN + n4 * 4;
    const float* feab    = fea + (size_t)sc * NN + sks * 8;

    // prefetch chunk 0
    float4 pfa[8];
#pragma unroll
    for (int r = 0; r < 8; r++)
        pfa[r] = *(const float4*)(adjbase + (size_t)r * 16 * NN);
    float4 pfe0, pfe1;   // (E,iE) for n = n4*4 .. n4*4+3
    {
        const float4* ep = (const float4*)(EIb + n4 * 4);
        pfe0 = ep[0]; pfe1 = ep[1];
    }
    float4 pff0 = *(const float4*)(feab);
    float4 pff1 = *(const float4*)(feab + 4);

    float acc[2][4][4];
#pragma unroll
    for (int mt = 0; mt < 2; mt++)
#pragma unroll
        for (int nt = 0; nt < 4; nt++)
#pragma unroll
            for (int i = 0; i < 4; i++) acc[mt][nt][i] = 0.f;

    const int swc   = (cr & 7) << 2;                         // construction swizzle
    const int sbase = ((sc >> 3) * 4 + sks) * 32 + (sc & 7) * 4;

    for (int ch = 0; ch < NCHUNK; ch++) {
        // ---- construct Ag tile into sA (coalesced, swizzled, tf32-rounded) ----
#pragma unroll
        for (int r = 0; r < 8; r++) {
            const float4 a = pfa[r];
            const float E = Em[r].x, I = Em[r].y;
            const float t0 = fmaxf(E * pfe0.y, pfe0.x * I);  // exp(|cm - cn|)
            const float t1 = fmaxf(E * pfe0.w, pfe0.z * I);
            const float t2 = fmaxf(E * pfe1.y, pfe1.x * I);
            const float t3 = fmaxf(E * pfe1.w, pfe1.z * I);
            float4 v;
            v.x = f2tff(__fdividef(a.x + a.x, 1.0f + t0));
            v.y = f2tff(__fdividef(a.y + a.y, 1.0f + t1));
            v.z = f2tff(__fdividef(a.z + a.z, 1.0f + t2));
            v.w = f2tff(__fdividef(a.w + a.w, 1.0f + t3));
            *(float4*)&sA[(r * 16 + cr) * 32 + ((n4 * 4) ^ swc)] = v;
        }
        // ---- stage fea fragments (pre-transposed to mma B layout) ----
        sB[sbase + 0] = make_float2(f2tff(pff0.x), f2tff(pff1.x));
        sB[sbase + 1] = make_float2(f2tff(pff0.y), f2tff(pff1.y));
        sB[sbase + 2] = make_float2(f2tff(pff0.z), f2tff(pff1.z));
        sB[sbase + 3] = make_float2(f2tff(pff0.w), f2tff(pff1.w));
        __syncthreads();

        // ---- prefetch next chunk (lands under the mma section) ----
        if (ch + 1 < NCHUNK) {
            const int n1 = (ch + 1) * KN;
#pragma unroll
            for (int r = 0; r < 8; r++)
                pfa[r] = *(const float4*)(adjbase + (size_t)r * 16 * NN + n1);
            const float4* ep = (const float4*)(EIb + n1 + n4 * 4);
            pfe0 = ep[0]; pfe1 = ep[1];
            pff0 = *(const float4*)(feab + n1);
            pff1 = *(const float4*)(feab + n1 + 4);
        }

        // ---- 32 mma per warp: 2 m-tiles x 4 ksteps x 4 c-tiles ----
#pragma unroll
        for (int mt = 0; mt < 2; mt++) {
            const float* pA = sA + (32 * w + mt * 16 + gr) * 32;
            const int swb = gr << 2;
#pragma unroll
            for (int ks = 0; ks < 4; ks++) {
                const uint32_t A0 = __float_as_uint(pA[((ks * 8)     ^ swb) + tc]);
                const uint32_t A1 = __float_as_uint(pA[256 + (((ks * 8)     ^ swb) + tc)]);
                const uint32_t A2 = __float_as_uint(pA[((ks * 8 + 4) ^ swb) + tc]);
                const uint32_t A3 = __float_as_uint(pA[256 + (((ks * 8 + 4) ^ swb) + tc)]);
#pragma unroll
                for (int nt = 0; nt < 4; nt++) {
                    const float2 bb = sB[(nt * 4 + ks) * 32 + lane];
                    const uint32_t B0 = __float_as_uint(bb.x);
                    const uint32_t B1 = __float_as_uint(bb.y);
                    asm volatile(
                        "mma.sync.aligned.m16n8k8.row.col.f32.tf32.tf32.f32 "
                        "{%0,%1,%2,%3}, {%4,%5,%6,%7}, {%8,%9}, {%0,%1,%2,%3};"
                        : "+f"(acc[mt][nt][0]), "+f"(acc[mt][nt][1]),
                          "+f"(acc[mt][nt][2]), "+f"(acc[mt][nt][3])
                        : "r"(A0), "r"(A1), "r"(A2), "r"(A3), "r"(B0), "r"(B1));
                }
            }
        }
        __syncthreads();
    }

    // ---- epilogue: para * acc, relu, direct STG ----
#pragma unroll
    for (int mt = 0; mt < 2; mt++) {
        const int mr0 = m0 + 32 * w + mt * 16 + gr;
        const int mr1 = mr0 + 8;
#pragma unroll
        for (int nt = 0; nt < 4; nt++) {
            const int cA = nt * 8 + 2 * tc;
            const int cB = cA + 1;
            out[(size_t)(b * CC + cA) * NN + mr0] = fmaxf(acc[mt][nt][0] * para[cA * NN + mr0], 0.f);
            out[(size_t)(b * CC + cB) * NN + mr0] = fmaxf(acc[mt][nt][1] * para[cB * NN + mr0], 0.f);
            out[(size_t)(b * CC + cA) * NN + mr1] = fmaxf(acc[mt][nt][2] * para[cA * NN + mr1], 0.f);
            out[(size_t)(b * CC + cB) * NN + mr1] = fmaxf(acc[mt][nt][3] * para[cB * NN + mr1], 0.f);
        }
    }
}

extern "C" void kernel_launch(void* const* d_in, const int* in_sizes, int n_in,
                              void* d_out, int out_size) {
    const float* x    = (const float*)d_in[0];  // [8,32,64,64]
    const float* para = (const float*)d_in[1];  // [1,32,64,64]
    const float* adj  = (const float*)d_in[2];  // [4096,4096]
    float* out = (float*)d_out;

    prep_kernel<<<(BB * NN) / 256, 256>>>(x);
    dim3 grid(NN / TM, BB);                     // 32 x 8 = 256 CTAs
    gcn_mma_kernel<<<grid, NTH>>>(x, para, adj, out);
}